// round 1
// baseline (speedup 1.0000x reference)
#include <cuda_runtime.h>
#include <cstdint>

#define E_NUM 60000
#define LDX   3712          // 29 * 128, row stride of x and out

// Rearranged, tf32-rounded weight scratch (static device globals: allowed)
__device__ float g_w0[896 * 896];
__device__ float g_w1[1536 * 1536];
__device__ float g_w2[1280 * 1280];

__device__ __forceinline__ float to_tf32(float x) {
    uint32_t u;
    asm("cvt.rna.tf32.f32 %0, %1;" : "=r"(u) : "f"(x));
    return __uint_as_float(u);
}

// ---------------- weight prep ----------------

__global__ void prep_copy_k(const float* __restrict__ src, int n) {
    int i = blockIdx.x * blockDim.x + threadIdx.x;
    if (i < n) g_w0[i] = to_tf32(src[i]);
}

// Build W' = [[Wr, Wi], [-Wi, Wr]] (2H x 2H) from src (H x 2H), tf32-rounded.
__global__ void prep_so2_k(const float* __restrict__ src, int H, int which) {
    float* dst = (which == 1) ? g_w1 : g_w2;
    const int W2 = 2 * H;
    const int total = W2 * W2;
    int i = blockIdx.x * blockDim.x + threadIdx.x;
    if (i >= total) return;
    int k = i / W2;
    int n = i - k * W2;
    float v;
    if (k < H) {
        v = src[k * W2 + n];                       // top: [Wr | Wi] = src
    } else {
        int kk = k - H;
        v = (n < H) ? -src[kk * W2 + n + H]        // bottom-left: -Wi
                    :  src[kk * W2 + n - H];       // bottom-right: Wr
    }
    dst[i] = to_tf32(v);
}

// ---------------- GEMM: C[m, n] = sum_k A[m*LDX + k] * W[k*N + n] (+bias) ----------------
// Tile 128x128x32, 256 threads, warps 4(M) x 2(N), warp tile 32x64.
// mma.sync.aligned.m16n8k8 tf32. Double-buffered smem, padded rows (conflict-free).

#define SMEM_BYTES 70656   // (2*128*36 + 2*32*132) * 4

__global__ __launch_bounds__(256) void gemm_tf32_k(
    const float* __restrict__ A, const float* __restrict__ bias,
    float* __restrict__ C, int M, int N, int K, int which)
{
    extern __shared__ float smem[];
    float* As = smem;            // [2][128][36]
    float* Bs = smem + 9216;     // [2][32][132]
    const float* __restrict__ Bw =
        (which == 0) ? g_w0 : (which == 1) ? g_w1 : g_w2;

    const int tid  = threadIdx.x;
    const int lane = tid & 31;
    const int warp = tid >> 5;
    const int wm   = warp >> 1;      // 0..3
    const int wn   = warp & 1;       // 0..1
    const int bn   = blockIdx.x;     // fastest: A tile L2-reused across N strip
    const int bm   = blockIdx.y;

    const int lr = lane >> 2;        // 0..7
    const int lc = lane & 3;         // 0..3

    float acc[2][8][4];
#pragma unroll
    for (int a = 0; a < 2; a++)
#pragma unroll
        for (int b = 0; b < 8; b++)
#pragma unroll
            for (int c = 0; c < 4; c++) acc[a][b][c] = 0.f;

    const int aRow0 = tid >> 3;           // + i*32
    const int aK4   = (tid & 7) * 4;
    const int bRow0 = tid >> 5;           // + i*8
    const int bN4   = (tid & 31) * 4;

    const int ktiles = K >> 5;

    float4 aReg[4], bReg[4];

    auto ldgA = [&](int kt) {
#pragma unroll
        for (int i = 0; i < 4; i++) {
            int m = bm * 128 + aRow0 + i * 32;
            if (m < M)
                aReg[i] = *reinterpret_cast<const float4*>(
                    A + (size_t)m * LDX + kt * 32 + aK4);
            else
                aReg[i] = make_float4(0.f, 0.f, 0.f, 0.f);
        }
    };
    auto ldgB = [&](int kt) {
#pragma unroll
        for (int i = 0; i < 4; i++) {
            int kr = kt * 32 + bRow0 + i * 8;
            bReg[i] = *reinterpret_cast<const float4*>(
                Bw + (size_t)kr * N + bn * 128 + bN4);
        }
    };
    auto sts = [&](int buf) {
        float* a = As + buf * 4608;
        float* b = Bs + buf * 4224;
#pragma unroll
        for (int i = 0; i < 4; i++) {
            float4 v = aReg[i];
            v.x = to_tf32(v.x); v.y = to_tf32(v.y);
            v.z = to_tf32(v.z); v.w = to_tf32(v.w);
            *reinterpret_cast<float4*>(a + (aRow0 + i * 32) * 36 + aK4) = v;
        }
#pragma unroll
        for (int i = 0; i < 4; i++)
            *reinterpret_cast<float4*>(b + (bRow0 + i * 8) * 132 + bN4) = bReg[i];
    };
    auto compute = [&](int buf) {
        const float* a = As + buf * 4608;
        const float* b = Bs + buf * 4224;
#pragma unroll
        for (int ks = 0; ks < 4; ks++) {
            const int k0 = ks * 8;
            uint32_t af[2][4];
#pragma unroll
            for (int im = 0; im < 2; im++) {
                int r  = wm * 32 + im * 16 + lr;
                int kc = k0 + lc;
                af[im][0] = __float_as_uint(a[r * 36 + kc]);
                af[im][1] = __float_as_uint(a[(r + 8) * 36 + kc]);
                af[im][2] = __float_as_uint(a[r * 36 + kc + 4]);
                af[im][3] = __float_as_uint(a[(r + 8) * 36 + kc + 4]);
            }
            uint32_t bf[8][2];
#pragma unroll
            for (int jn = 0; jn < 8; jn++) {
                int cn = wn * 64 + jn * 8 + lr;
                bf[jn][0] = __float_as_uint(b[(k0 + lc) * 132 + cn]);
                bf[jn][1] = __float_as_uint(b[(k0 + 4 + lc) * 132 + cn]);
            }
#pragma unroll
            for (int im = 0; im < 2; im++)
#pragma unroll
                for (int jn = 0; jn < 8; jn++) {
                    asm volatile(
                        "mma.sync.aligned.m16n8k8.row.col.f32.tf32.tf32.f32 "
                        "{%0,%1,%2,%3}, {%4,%5,%6,%7}, {%8,%9}, {%0,%1,%2,%3};\n"
                        : "+f"(acc[im][jn][0]), "+f"(acc[im][jn][1]),
                          "+f"(acc[im][jn][2]), "+f"(acc[im][jn][3])
                        : "r"(af[im][0]), "r"(af[im][1]),
                          "r"(af[im][2]), "r"(af[im][3]),
                          "r"(bf[jn][0]), "r"(bf[jn][1]));
                }
        }
    };

    ldgA(0); ldgB(0); sts(0);
    __syncthreads();
    int buf = 0;
    for (int kt = 0; kt < ktiles; kt++) {
        if (kt + 1 < ktiles) { ldgA(kt + 1); ldgB(kt + 1); }
        compute(buf);
        if (kt + 1 < ktiles) {
            sts(buf ^ 1);
            __syncthreads();
        }
        buf ^= 1;
    }

    // epilogue
#pragma unroll
    for (int im = 0; im < 2; im++) {
        int r0 = bm * 128 + wm * 32 + im * 16 + lr;
#pragma unroll
        for (int jn = 0; jn < 8; jn++) {
            int cg = bn * 128 + wn * 64 + jn * 8 + lc * 2;
            float bv0 = 0.f, bv1 = 0.f;
            if (bias) { bv0 = bias[cg]; bv1 = bias[cg + 1]; }
            if (r0 < M) {
                float2 v; v.x = acc[im][jn][0] + bv0; v.y = acc[im][jn][1] + bv1;
                *reinterpret_cast<float2*>(C + (size_t)r0 * LDX + cg) = v;
            }
            if (r0 + 8 < M) {
                float2 v; v.x = acc[im][jn][2] + bv0; v.y = acc[im][jn][3] + bv1;
                *reinterpret_cast<float2*>(C + (size_t)(r0 + 8) * LDX + cg) = v;
            }
        }
    }
}

// ---------------- launch ----------------

extern "C" void kernel_launch(void* const* d_in, const int* in_sizes, int n_in,
                              void* d_out, int out_size)
{
    const float* x  = (const float*)d_in[0];
    // d_in[1] = x_edge: unused by the reference
    const float* w0 = (const float*)d_in[2];
    const float* b0 = (const float*)d_in[3];
    const float* w1 = (const float*)d_in[4];
    const float* w2 = (const float*)d_in[5];
    float* out = (float*)d_out;

    // Weight prep (cheap; re-run every replay for determinism)
    prep_copy_k<<<(896 * 896 + 255) / 256, 256>>>(w0, 896 * 896);
    prep_so2_k<<<(4 * 768 * 768 + 255) / 256, 256>>>(w1, 768, 1);
    prep_so2_k<<<(4 * 640 * 640 + 255) / 256, 256>>>(w2, 640, 2);

    cudaFuncSetAttribute(gemm_tf32_k,
                         cudaFuncAttributeMaxDynamicSharedMemorySize, SMEM_BYTES);

    const int mb = (E_NUM + 127) / 128;   // 469
    // m=0: (E,896) @ (896,896) + bias  -> out rows 0..6
    gemm_tf32_k<<<dim3(896 / 128, mb), 256, SMEM_BYTES>>>(
        x, b0, out, E_NUM, 896, 896, 0);
    // m=1: (E,1536) @ (1536,1536)      -> out rows 7..18
    gemm_tf32_k<<<dim3(1536 / 128, mb), 256, SMEM_BYTES>>>(
        x + 896, nullptr, out + 896, E_NUM, 1536, 1536, 1);
    // m=2: (E,1280) @ (1280,1280)      -> out rows 19..28
    gemm_tf32_k<<<dim3(1280 / 128, mb), 256, SMEM_BYTES>>>(
        x + 2432, nullptr, out + 2432, E_NUM, 1280, 1280, 2);
}

// round 9
// speedup vs baseline: 1.2222x; 1.2222x over previous
#include <cuda_runtime.h>
#include <cstdint>

#define E_NUM 60000
#define LDX   3712          // 29 * 128, row stride of x and out

// tf32-rounded weights, [k][n] row-major (static device globals: allowed)
__device__ float g_w0[896 * 896];
__device__ float g_w1[1536 * 1536];
__device__ float g_w2[1280 * 1280];

__device__ __forceinline__ float to_tf32(float x) {
    uint32_t u;
    asm("cvt.rna.tf32.f32 %0, %1;" : "=r"(u) : "f"(x));
    return __uint_as_float(u);
}

// ---------------- weight prep (rna-rounded, [k][n]) ----------------

__global__ void prep_copy_k(const float* __restrict__ src, int n) {
    int i = blockIdx.x * blockDim.x + threadIdx.x;
    if (i < n) g_w0[i] = to_tf32(src[i]);
}
// W' = [[Wa, Wb], [-Wb, Wa]] (2H x 2H) from src (H x 2H), tf32-rounded.
__global__ void prep_so2_k(const float* __restrict__ src, int H, int which) {
    float* dst = (which == 1) ? g_w1 : g_w2;
    const int W2 = 2 * H;
    int i = blockIdx.x * blockDim.x + threadIdx.x;
    if (i >= W2 * W2) return;
    int k = i / W2;
    int n = i - k * W2;
    float v;
    if (k < H) {
        v = src[k * W2 + n];
    } else {
        int kk = k - H;
        v = (n < H) ? -src[kk * W2 + n + H] : src[kk * W2 + n - H];
    }
    dst[i] = to_tf32(v);
}

// ---------------- GEMM: C = A(ExK, ld LDX) * W(KxN) (+bias) ----------------
// Block tile 256x128x32, 256 threads, warp grid 4(M)x2(N), warp tile 64x64.
// A and B both: LDG -> STS, double buffered (R1's proven path, no cp.async).
// Smem: As[2][256][36], Bs[2][32][132]; pads keep every access conflict-free.

#define AS_STRIDE 36
#define BS_STRIDE 132
#define AS_BUF (256 * AS_STRIDE)    // 9216 floats
#define BS_BUF (32 * BS_STRIDE)     // 4224 floats
#define SMEM_BYTES ((2 * AS_BUF + 2 * BS_BUF) * 4)   // 107520

__global__ __launch_bounds__(256) void gemm_tf32_k(
    const float* __restrict__ A, const float* __restrict__ Bw,
    const float* __restrict__ bias, float* __restrict__ C,
    int N, int K)
{
    extern __shared__ float smem[];
    float* As = smem;                  // [2][256][36]
    float* Bs = smem + 2 * AS_BUF;     // [2][32][132]

    const int tid  = threadIdx.x;
    const int lane = tid & 31;
    const int warp = tid >> 5;
    const int wm   = warp >> 1;        // 0..3  (64-row strip)
    const int wn   = warp & 1;         // 0..1  (64-col strip)
    const int bn   = blockIdx.x;       // fastest: A tile L2-reused across N strip
    const int bm   = blockIdx.y;

    const int lr = lane >> 2;          // 0..7
    const int lc = lane & 3;           // 0..3

    float acc[4][8][4];
#pragma unroll
    for (int a = 0; a < 4; a++)
#pragma unroll
        for (int b = 0; b < 8; b++)
#pragma unroll
            for (int c = 0; c < 4; c++) acc[a][b][c] = 0.f;

    const int ar   = tid >> 3;         // A chunk row base (+32*i)
    const int asub = tid & 7;          // A 16B sub-chunk
    const int br   = tid >> 5;         // B row base (+8*i)
    const int bsub = tid & 31;         // B 16B sub-chunk (0..31)

    const int ktiles = K >> 5;

    float4 aReg[8], bReg[4];

    auto ldgA = [&](int kt) {
#pragma unroll
        for (int i = 0; i < 8; i++) {
            int m = bm * 256 + ar + i * 32;
            if (m < E_NUM)
                aReg[i] = *reinterpret_cast<const float4*>(
                    A + (size_t)m * LDX + kt * 32 + asub * 4);
            else
                aReg[i] = make_float4(0.f, 0.f, 0.f, 0.f);
        }
    };
    // B tile: 32 rows x 128 floats; thread covers rows br, br+8, br+16, br+24.
    auto ldgB = [&](int kt) {
#pragma unroll
        for (int i = 0; i < 4; i++) {
            int kr = kt * 32 + br + i * 8;
            bReg[i] = *reinterpret_cast<const float4*>(
                Bw + (size_t)kr * N + bn * 128 + bsub * 4);
        }
    };
    auto stsA = [&](int buf) {
        float* a = As + buf * AS_BUF;
#pragma unroll
        for (int i = 0; i < 8; i++) {
            float4 v = aReg[i];
            v.x = to_tf32(v.x); v.y = to_tf32(v.y);
            v.z = to_tf32(v.z); v.w = to_tf32(v.w);
            *reinterpret_cast<float4*>(a + (ar + i * 32) * AS_STRIDE + asub * 4) = v;
        }
    };
    auto stsB = [&](int buf) {
        float* b = Bs + buf * BS_BUF;
#pragma unroll
        for (int i = 0; i < 4; i++)
            *reinterpret_cast<float4*>(b + (br + i * 8) * BS_STRIDE + bsub * 4) = bReg[i];
    };
    auto compute = [&](int buf) {
        const float* a = As + buf * AS_BUF;
        const float* b = Bs + buf * BS_BUF;
#pragma unroll
        for (int ks = 0; ks < 4; ks++) {
            const int k0 = ks * 8;
            uint32_t af[4][4];
#pragma unroll
            for (int im = 0; im < 4; im++) {
                int r  = wm * 64 + im * 16 + lr;
                int kc = k0 + lc;
                af[im][0] = __float_as_uint(a[r * AS_STRIDE + kc]);
                af[im][1] = __float_as_uint(a[(r + 8) * AS_STRIDE + kc]);
                af[im][2] = __float_as_uint(a[r * AS_STRIDE + kc + 4]);
                af[im][3] = __float_as_uint(a[(r + 8) * AS_STRIDE + kc + 4]);
            }
            uint32_t bf[8][2];
#pragma unroll
            for (int jn = 0; jn < 8; jn++) {
                int cn = wn * 64 + jn * 8 + lr;
                bf[jn][0] = __float_as_uint(b[(k0 + lc) * BS_STRIDE + cn]);
                bf[jn][1] = __float_as_uint(b[(k0 + 4 + lc) * BS_STRIDE + cn]);
            }
#pragma unroll
            for (int im = 0; im < 4; im++)
#pragma unroll
                for (int jn = 0; jn < 8; jn++) {
                    asm volatile(
                        "mma.sync.aligned.m16n8k8.row.col.f32.tf32.tf32.f32 "
                        "{%0,%1,%2,%3}, {%4,%5,%6,%7}, {%8,%9}, {%0,%1,%2,%3};\n"
                        : "+f"(acc[im][jn][0]), "+f"(acc[im][jn][1]),
                          "+f"(acc[im][jn][2]), "+f"(acc[im][jn][3])
                        : "r"(af[im][0]), "r"(af[im][1]),
                          "r"(af[im][2]), "r"(af[im][3]),
                          "r"(bf[jn][0]), "r"(bf[jn][1]));
                }
        }
    };

    // prologue
    ldgA(0); ldgB(0);
    stsA(0); stsB(0);
    __syncthreads();

    int buf = 0;
    for (int kt = 0; kt < ktiles; kt++) {
        if (kt + 1 < ktiles) { ldgA(kt + 1); ldgB(kt + 1); }
        compute(buf);
        if (kt + 1 < ktiles) {
            stsA(buf ^ 1); stsB(buf ^ 1);
            __syncthreads();
        }
        buf ^= 1;
    }

    // epilogue
#pragma unroll
    for (int im = 0; im < 4; im++) {
        int r0 = bm * 256 + wm * 64 + im * 16 + lr;
#pragma unroll
        for (int jn = 0; jn < 8; jn++) {
            int cg = bn * 128 + wn * 64 + jn * 8 + lc * 2;
            float bv0 = 0.f, bv1 = 0.f;
            if (bias) { bv0 = bias[cg]; bv1 = bias[cg + 1]; }
            if (r0 < E_NUM) {
                float2 v; v.x = acc[im][jn][0] + bv0; v.y = acc[im][jn][1] + bv1;
                *reinterpret_cast<float2*>(C + (size_t)r0 * LDX + cg) = v;
            }
            if (r0 + 8 < E_NUM) {
                float2 v; v.x = acc[im][jn][2] + bv0; v.y = acc[im][jn][3] + bv1;
                *reinterpret_cast<float2*>(C + (size_t)(r0 + 8) * LDX + cg) = v;
            }
        }
    }
}

// ---------------- launch ----------------

extern "C" void kernel_launch(void* const* d_in, const int* in_sizes, int n_in,
                              void* d_out, int out_size)
{
    const float* x  = (const float*)d_in[0];
    // d_in[1] = x_edge: unused by the reference
    const float* w0 = (const float*)d_in[2];
    const float* b0 = (const float*)d_in[3];
    const float* w1 = (const float*)d_in[4];
    const float* w2 = (const float*)d_in[5];
    float* out = (float*)d_out;

    prep_copy_k<<<(896 * 896 + 255) / 256, 256>>>(w0, 896 * 896);
    prep_so2_k<<<(1536 * 1536 + 255) / 256, 256>>>(w1, 768, 1);
    prep_so2_k<<<(1280 * 1280 + 255) / 256, 256>>>(w2, 640, 2);

    float *pw0, *pw1, *pw2;
    cudaGetSymbolAddress((void**)&pw0, g_w0);
    cudaGetSymbolAddress((void**)&pw1, g_w1);
    cudaGetSymbolAddress((void**)&pw2, g_w2);

    cudaFuncSetAttribute(gemm_tf32_k,
                         cudaFuncAttributeMaxDynamicSharedMemorySize, SMEM_BYTES);

    const int mb = (E_NUM + 255) / 256;   // 235
    // m=0: (E,896) @ (896,896) + bias  -> out cols 0..895
    gemm_tf32_k<<<dim3(7, mb), 256, SMEM_BYTES>>>(x,        pw0, b0,      out,        896,  896);
    // m=1: (E,1536) @ (1536,1536)      -> out cols 896..2431
    gemm_tf32_k<<<dim3(12, mb), 256, SMEM_BYTES>>>(x + 896,  pw1, nullptr, out + 896,  1536, 1536);
    // m=2: (E,1280) @ (1280,1280)      -> out cols 2432..3711
    gemm_tf32_k<<<dim3(10, mb), 256, SMEM_BYTES>>>(x + 2432, pw2, nullptr, out + 2432, 1280, 1280);
}

// round 10
// speedup vs baseline: 1.5072x; 1.2332x over previous
#include <cuda_runtime.h>
#include <cstdint>

#define E_NUM 60000
#define LDX   3712          // 29 * 128, row stride of x and out

// tf32-rounded weights, [k][n] row-major (static device globals: allowed)
__device__ float g_w0[896 * 896];
__device__ float g_w1[1536 * 1536];
__device__ float g_w2[1280 * 1280];

__device__ __forceinline__ float to_tf32(float x) {
    uint32_t u;
    asm("cvt.rna.tf32.f32 %0, %1;" : "=r"(u) : "f"(x));
    return __uint_as_float(u);
}

// ---------------- weight prep (rna-rounded, [k][n]) ----------------

__global__ void prep_copy_k(const float* __restrict__ src, int n) {
    int i = blockIdx.x * blockDim.x + threadIdx.x;
    if (i < n) g_w0[i] = to_tf32(src[i]);
}
// W' = [[Wa, Wb], [-Wb, Wa]] (2H x 2H) from src (H x 2H), tf32-rounded.
__global__ void prep_so2_k(const float* __restrict__ src, int H, int which) {
    float* dst = (which == 1) ? g_w1 : g_w2;
    const int W2 = 2 * H;
    int i = blockIdx.x * blockDim.x + threadIdx.x;
    if (i >= W2 * W2) return;
    int k = i / W2;
    int n = i - k * W2;
    float v;
    if (k < H) {
        v = src[k * W2 + n];
    } else {
        int kk = k - H;
        v = (n < H) ? -src[kk * W2 + n + H] : src[kk * W2 + n - H];
    }
    dst[i] = to_tf32(v);
}

// ---------------- GEMM: C = A(ExK, ld LDX) * W(KxN) (+bias) ----------------
// Block tile 128x128x32, 128 threads (4 warps), warp grid 2x2, warp tile 64x64.
// 2 CTAs/SM (regs+smem sized for it) so sync bubbles of one CTA overlap the
// other's MMAs. B smem stride 136 -> conflict-free fragment loads
// (bank = 8*lc + lr + 8*jn mod 32, a permutation). A/B via LDG->STS.

#define AS_STRIDE 36
#define BS_STRIDE 136
#define AS_BUF (128 * AS_STRIDE)    // 4608 floats
#define BS_BUF (32 * BS_STRIDE)     // 4352 floats
#define SMEM_BYTES ((2 * AS_BUF + 2 * BS_BUF) * 4)   // 71680

__global__ __launch_bounds__(128, 2) void gemm_tf32_k(
    const float* __restrict__ A, const float* __restrict__ Bw,
    const float* __restrict__ bias, float* __restrict__ C,
    int N, int K)
{
    extern __shared__ float smem[];
    float* As = smem;                  // [2][128][36]
    float* Bs = smem + 2 * AS_BUF;     // [2][32][136]

    const int tid  = threadIdx.x;
    const int lane = tid & 31;
    const int warp = tid >> 5;         // 0..3
    const int wm   = warp >> 1;        // 0..1  (64-row strip)
    const int wn   = warp & 1;         // 0..1  (64-col strip)
    const int bn   = blockIdx.x;       // fastest: A tile L2-reused across N strip
    const int bm   = blockIdx.y;

    const int lr = lane >> 2;          // 0..7
    const int lc = lane & 3;           // 0..3

    float acc[4][8][4];
#pragma unroll
    for (int a = 0; a < 4; a++)
#pragma unroll
        for (int b = 0; b < 8; b++)
#pragma unroll
            for (int c = 0; c < 4; c++) acc[a][b][c] = 0.f;

    const int ar   = tid >> 3;         // A row base (0..15), rows ar + i*16
    const int asub = tid & 7;          // A 16B sub-chunk
    const int br   = warp;             // B row base: warp w covers rows w + i*4
    const int bsub = lane;             // B 16B sub-chunk (0..31)

    const int ktiles = K >> 5;

    float4 aReg[8], bReg[4];

    auto ldgA = [&](int kt) {
#pragma unroll
        for (int i = 0; i < 8; i++) {
            int m = bm * 128 + ar + i * 16;
            if (m < E_NUM)
                aReg[i] = *reinterpret_cast<const float4*>(
                    A + (size_t)m * LDX + kt * 32 + asub * 4);
            else
                aReg[i] = make_float4(0.f, 0.f, 0.f, 0.f);
        }
    };
    // B tile 32x128: rows br + i*4; half h=0 -> i 0..3 (rows 0..15), h=1 -> 16..31
    auto ldgB = [&](int kt, int h) {
#pragma unroll
        for (int i = 0; i < 4; i++) {
            int kr = kt * 32 + br + (i + h * 4) * 4;
            bReg[i] = *reinterpret_cast<const float4*>(
                Bw + (size_t)kr * N + bn * 128 + bsub * 4);
        }
    };
    auto stsA = [&](int buf) {
        float* a = As + buf * AS_BUF;
#pragma unroll
        for (int i = 0; i < 8; i++) {
            float4 v = aReg[i];
            v.x = to_tf32(v.x); v.y = to_tf32(v.y);
            v.z = to_tf32(v.z); v.w = to_tf32(v.w);
            *reinterpret_cast<float4*>(a + (ar + i * 16) * AS_STRIDE + asub * 4) = v;
        }
    };
    auto stsB = [&](int buf, int h) {
        float* b = Bs + buf * BS_BUF;
#pragma unroll
        for (int i = 0; i < 4; i++)
            *reinterpret_cast<float4*>(
                b + (br + (i + h * 4) * 4) * BS_STRIDE + bsub * 4) = bReg[i];
    };
    auto compute_ks = [&](int buf, int ks) {
        const float* a = As + buf * AS_BUF;
        const float* b = Bs + buf * BS_BUF;
        const int k0 = ks * 8;
        uint32_t af[4][4];
#pragma unroll
        for (int im = 0; im < 4; im++) {
            int r  = wm * 64 + im * 16 + lr;
            int kc = k0 + lc;
            af[im][0] = __float_as_uint(a[r * AS_STRIDE + kc]);
            af[im][1] = __float_as_uint(a[(r + 8) * AS_STRIDE + kc]);
            af[im][2] = __float_as_uint(a[r * AS_STRIDE + kc + 4]);
            af[im][3] = __float_as_uint(a[(r + 8) * AS_STRIDE + kc + 4]);
        }
        uint32_t bf[8][2];
#pragma unroll
        for (int jn = 0; jn < 8; jn++) {
            int cn = wn * 64 + jn * 8 + lr;
            bf[jn][0] = __float_as_uint(b[(k0 + lc) * BS_STRIDE + cn]);
            bf[jn][1] = __float_as_uint(b[(k0 + 4 + lc) * BS_STRIDE + cn]);
        }
#pragma unroll
        for (int im = 0; im < 4; im++)
#pragma unroll
            for (int jn = 0; jn < 8; jn++) {
                asm volatile(
                    "mma.sync.aligned.m16n8k8.row.col.f32.tf32.tf32.f32 "
                    "{%0,%1,%2,%3}, {%4,%5,%6,%7}, {%8,%9}, {%0,%1,%2,%3};\n"
                    : "+f"(acc[im][jn][0]), "+f"(acc[im][jn][1]),
                      "+f"(acc[im][jn][2]), "+f"(acc[im][jn][3])
                    : "r"(af[im][0]), "r"(af[im][1]),
                      "r"(af[im][2]), "r"(af[im][3]),
                      "r"(bf[jn][0]), "r"(bf[jn][1]));
            }
    };

    // prologue
    ldgA(0); ldgB(0, 0);
    stsA(0); stsB(0, 0);
    ldgB(0, 1);
    stsB(0, 1);
    __syncthreads();

    int buf = 0;
    for (int kt = 0; kt < ktiles; kt++) {
        const bool nxt = (kt + 1 < ktiles);
        if (nxt) { ldgA(kt + 1); ldgB(kt + 1, 0); }
        compute_ks(buf, 0);
        compute_ks(buf, 1);
        if (nxt) { stsB(buf ^ 1, 0); ldgB(kt + 1, 1); }
        compute_ks(buf, 2);
        compute_ks(buf, 3);
        if (nxt) {
            stsA(buf ^ 1); stsB(buf ^ 1, 1);
            __syncthreads();
        }
        buf ^= 1;
    }

    // epilogue
#pragma unroll
    for (int im = 0; im < 4; im++) {
        int r0 = bm * 128 + wm * 64 + im * 16 + lr;
#pragma unroll
        for (int jn = 0; jn < 8; jn++) {
            int cg = bn * 128 + wn * 64 + jn * 8 + lc * 2;
            float bv0 = 0.f, bv1 = 0.f;
            if (bias) { bv0 = bias[cg]; bv1 = bias[cg + 1]; }
            if (r0 < E_NUM) {
                float2 v; v.x = acc[im][jn][0] + bv0; v.y = acc[im][jn][1] + bv1;
                *reinterpret_cast<float2*>(C + (size_t)r0 * LDX + cg) = v;
            }
            if (r0 + 8 < E_NUM) {
                float2 v; v.x = acc[im][jn][2] + bv0; v.y = acc[im][jn][3] + bv1;
                *reinterpret_cast<float2*>(C + (size_t)(r0 + 8) * LDX + cg) = v;
            }
        }
    }
}

// ---------------- launch ----------------

extern "C" void kernel_launch(void* const* d_in, const int* in_sizes, int n_in,
                              void* d_out, int out_size)
{
    const float* x  = (const float*)d_in[0];
    // d_in[1] = x_edge: unused by the reference
    const float* w0 = (const float*)d_in[2];
    const float* b0 = (const float*)d_in[3];
    const float* w1 = (const float*)d_in[4];
    const float* w2 = (const float*)d_in[5];
    float* out = (float*)d_out;

    prep_copy_k<<<(896 * 896 + 255) / 256, 256>>>(w0, 896 * 896);
    prep_so2_k<<<(1536 * 1536 + 255) / 256, 256>>>(w1, 768, 1);
    prep_so2_k<<<(1280 * 1280 + 255) / 256, 256>>>(w2, 640, 2);

    float *pw0, *pw1, *pw2;
    cudaGetSymbolAddress((void**)&pw0, g_w0);
    cudaGetSymbolAddress((void**)&pw1, g_w1);
    cudaGetSymbolAddress((void**)&pw2, g_w2);

    cudaFuncSetAttribute(gemm_tf32_k,
                         cudaFuncAttributeMaxDynamicSharedMemorySize, SMEM_BYTES);

    const int mb = (E_NUM + 127) / 128;   // 469
    // m=0: (E,896) @ (896,896) + bias  -> out cols 0..895
    gemm_tf32_k<<<dim3(7, mb), 128, SMEM_BYTES>>>(x,        pw0, b0,      out,        896,  896);
    // m=1: (E,1536) @ (1536,1536)      -> out cols 896..2431
    gemm_tf32_k<<<dim3(12, mb), 128, SMEM_BYTES>>>(x + 896,  pw1, nullptr, out + 896,  1536, 1536);
    // m=2: (E,1280) @ (1280,1280)      -> out cols 2432..3711
    gemm_tf32_k<<<dim3(10, mb), 128, SMEM_BYTES>>>(x + 2432, pw2, nullptr, out + 2432, 1280, 1280);
}